// round 4
// baseline (speedup 1.0000x reference)
#include <cuda_runtime.h>
#include <math.h>

// ---------------------------------------------------------------------------
// Problem constants
// ---------------------------------------------------------------------------
#define HH 192
#define WW 192
#define HW (192*192)
#define BB 4
#define DD 8
#define ICT 40          // conv input channels (always 40 = NF + 8)
#define TILE 32

// ---------------------------------------------------------------------------
// Scratch (device globals — no allocation allowed)
// ---------------------------------------------------------------------------
__device__ float g_h   [BB*8 *HW];   // h state
__device__ float g_c   [BB*8 *HW];   // c state
__device__ float g_r   [BB*40*HW];   // r = [cs, sigmoid(q)]
__device__ float g_gate[BB*56*HW];   // raw gate conv output
__device__ float g_x0  [BB*40*HW];   // raw conv0 output
__device__ float g_x1  [BB*40*HW];   // raw conv1 output
__device__ float g_Wg  [56*40*3*3];  // packed gate weights [oc][ic][ky][kx]
__device__ float g_bg  [56];
__device__ float g_Wh2 [11*40*5*5];  // packed head weights (Wh padded to 5x5 | W2)
__device__ float g_bh2 [11];
__device__ float g_sc0[40], g_sh0[40], g_sc1[40], g_sh1[40];  // BN scale/shift

__device__ __forceinline__ float sigmoidf_(float x) { return 1.f / (1.f + expf(-x)); }

// ---------------------------------------------------------------------------
// Zero the recurrent state
// ---------------------------------------------------------------------------
__global__ void zero_state_kernel() {
    int i = blockIdx.x * blockDim.x + threadIdx.x;
    if (i < BB*8*HW) { g_h[i] = 0.f; g_c[i] = 0.f; }
}

// ---------------------------------------------------------------------------
// Pack weights: gates (Wf|Wi|Wc|Wq -> 56 oc) and head (Wh centered in 5x5 | W2)
// ---------------------------------------------------------------------------
__global__ void prep_weights_kernel(
    const float* __restrict__ Wf, const float* __restrict__ bf,
    const float* __restrict__ Wi, const float* __restrict__ bi,
    const float* __restrict__ Wc, const float* __restrict__ bc,
    const float* __restrict__ Wq, const float* __restrict__ bq,
    const float* __restrict__ Wh, const float* __restrict__ bh,
    const float* __restrict__ W2, const float* __restrict__ b2)
{
    int i = blockIdx.x * blockDim.x + threadIdx.x;
    const int NG = 56*40*9;
    if (i < NG) {
        int oc = i / 360, r = i % 360;
        float v;
        if      (oc < 8 ) v = Wf[ oc     *360 + r];
        else if (oc < 16) v = Wi[(oc-8 ) *360 + r];
        else if (oc < 24) v = Wc[(oc-16) *360 + r];
        else              v = Wq[(oc-24) *360 + r];
        g_Wg[i] = v;
    }
    if (i < 56) {
        g_bg[i] = (i < 8) ? bf[i] : (i < 16) ? bi[i-8] : (i < 24) ? bc[i-16] : bq[i-24];
    }
    const int NH = 11*40*25;
    if (i < NH) {
        int oc = i / 1000, r = i % 1000, c = r / 25, k = r % 25, ky = k / 5, kx = k % 5;
        float v = 0.f;
        if (oc < 8) {
            if (ky >= 1 && ky <= 3 && kx >= 1 && kx <= 3)
                v = Wh[((oc*40 + c)*3 + (ky-1))*3 + (kx-1)];
        } else {
            v = W2[(((oc-8)*40 + c)*5 + ky)*5 + kx];
        }
        g_Wh2[i] = v;
    }
    if (i < 11) g_bh2[i] = (i < 8) ? bh[i] : b2[i-8];
}

// ---------------------------------------------------------------------------
// Generic direct conv.
//  K      : kernel size (3 or 5), pad = K/2
//  OCT    : total output channels
//  MODE   : 0 = store raw to out (B,OCT,H,W)
//           1 = head: oc<8 -> out (h state, B,8,H,W); oc in [8,11) -> out_o
//               at ((b*3+(oc-8))*DD + t)*HW + pix
//  Input: channels [0,c_split) from in1 (batch stride bs1),
//         channels [c_split,40) from in2 (batch stride bs2).
//  Optional per-channel input transform:  v = max(v*isc[c]+ish[c], 0)  (BN+ReLU)
//  Tiling: 32x32 output pixels, 8 oc per block, 256 threads,
//          each thread: 4 pixels (y strided by 8) x 8 oc register tile.
// ---------------------------------------------------------------------------
template<int K, int OCT, int MODE>
__global__ __launch_bounds__(256, 2)
void conv_kernel(
    const float* __restrict__ in1, long bs1,
    const float* __restrict__ in2, long bs2, int c_split,
    const float* __restrict__ Wt,  const float* __restrict__ bias,
    const float* __restrict__ isc, const float* __restrict__ ish,
    float* __restrict__ out, float* __restrict__ out_o, int t)
{
    constexpr int PS  = TILE + K - 1;
    constexpr int PAD = K / 2;
    constexpr int NGROUP = (OCT + 7) / 8;

    __shared__ __align__(16) float patch[8 * PS * PS];
    __shared__ __align__(16) float wts  [8 * K * K * 8];

    const int b   = blockIdx.z / NGROUP;
    const int g   = blockIdx.z % NGROUP;
    const int tx0 = blockIdx.x * TILE;
    const int ty0 = blockIdx.y * TILE;
    const int tid = threadIdx.x;
    const int x   = tid & 31;
    const int y0  = tid >> 5;          // 0..7

    float acc[4][8];
    #pragma unroll
    for (int o = 0; o < 8; ++o) {
        int oc = g*8 + o;
        float bini = (bias != nullptr && oc < OCT) ? __ldg(&bias[oc]) : 0.f;
        #pragma unroll
        for (int p = 0; p < 4; ++p) acc[p][o] = bini;
    }

    for (int chunk = 0; chunk < 5; ++chunk) {
        __syncthreads();
        // ---- load input patch (8 channels) ----
        for (int idx = tid; idx < 8*PS*PS; idx += 256) {
            int c  = idx / (PS*PS);
            int r  = idx - c*PS*PS;
            int yy = r / PS, xx = r - yy*PS;
            int gy = ty0 + yy - PAD, gx = tx0 + xx - PAD;
            float v = 0.f;
            if ((unsigned)gy < HH && (unsigned)gx < WW) {
                int cg = chunk*8 + c;
                const float* src; int cc;
                if (cg < c_split) { src = in1 + (long)b*bs1; cc = cg; }
                else              { src = in2 + (long)b*bs2; cc = cg - c_split; }
                v = __ldg(src + (long)cc*HW + gy*WW + gx);
                if (isc != nullptr) v = fmaxf(v * isc[cg] + ish[cg], 0.f);
            }
            patch[idx] = v;
        }
        // ---- load weight chunk: layout ((c*K+ky)*K+kx)*8 + oc ----
        for (int idx = tid; idx < 8*K*K*8; idx += 256) {
            int oc   = idx & 7;
            int rest = idx >> 3;
            int kx = rest % K; rest /= K;
            int ky = rest % K;
            int c  = rest / K;
            int ocg = g*8 + oc;
            float wv = 0.f;
            if (ocg < OCT)
                wv = __ldg(&Wt[((long)ocg*ICT + chunk*8 + c)*K*K + ky*K + kx]);
            wts[idx] = wv;
        }
        __syncthreads();
        // ---- compute ----
        #pragma unroll 1
        for (int c = 0; c < 8; ++c) {
            const float* pc_ = &patch[c*PS*PS];
            #pragma unroll
            for (int ky = 0; ky < K; ++ky) {
                #pragma unroll
                for (int kx = 0; kx < K; ++kx) {
                    const float* wp = &wts[((c*K + ky)*K + kx)*8];
                    float w8[8];
                    *(float4*)&w8[0] = *(const float4*)wp;
                    *(float4*)&w8[4] = *(const float4*)(wp + 4);
                    float iv[4];
                    #pragma unroll
                    for (int p = 0; p < 4; ++p)
                        iv[p] = pc_[(y0 + p*8 + ky)*PS + x + kx];
                    #pragma unroll
                    for (int p = 0; p < 4; ++p)
                        #pragma unroll
                        for (int o = 0; o < 8; ++o)
                            acc[p][o] = fmaf(iv[p], w8[o], acc[p][o]);
                }
            }
        }
    }

    // ---- store ----
    #pragma unroll
    for (int p = 0; p < 4; ++p) {
        int y   = ty0 + y0 + p*8;
        int pix = y*WW + tx0 + x;
        #pragma unroll
        for (int o = 0; o < 8; ++o) {
            int oc = g*8 + o;
            if (oc >= OCT) continue;
            float v = acc[p][o];
            if (MODE == 0) {
                out[((long)b*OCT + oc)*HW + pix] = v;
            } else {
                if (oc < 8) out[((long)b*8 + oc)*HW + pix] = v;
                else        out_o[(((long)b*3 + (oc-8))*DD + t)*HW + pix] = v;
            }
        }
    }
}

// ---------------------------------------------------------------------------
// LSTM pointwise update:
//  f,i,g,q from raw gates; c' = sig(f)*c + sig(i)*tanh(g);
//  r[0:8]=c', r[8:40]=sig(q)
// ---------------------------------------------------------------------------
__global__ void lstm_update_kernel(const float* __restrict__ gates,
                                   float* __restrict__ cbuf,
                                   float* __restrict__ rbuf)
{
    int i = blockIdx.x * blockDim.x + threadIdx.x;
    if (i >= BB*HW) return;
    int b = i / HW, p = i - b*HW;
    const float* G = gates + (long)b*56*HW + p;
    float*       C = cbuf  + (long)b*8 *HW + p;
    float*       R = rbuf  + (long)b*40*HW + p;
    #pragma unroll
    for (int c = 0; c < 8; ++c) {
        float f  = sigmoidf_(G[(c     )*HW]);
        float ii = sigmoidf_(G[(c + 8 )*HW]);
        float gg = tanhf    (G[(c + 16)*HW]);
        float cs = f * C[c*HW] + ii * gg;
        C[c*HW] = cs;
        R[c*HW] = cs;
    }
    #pragma unroll
    for (int c = 0; c < 32; ++c)
        R[(8 + c)*HW] = sigmoidf_(G[(24 + c)*HW]);
}

// ---------------------------------------------------------------------------
// Deterministic training-mode BN stats: one block per channel.
// Produces scale = gamma*rsqrt(var+eps), shift = beta - mean*scale.
// ---------------------------------------------------------------------------
__global__ void bn_stats_kernel(const float* __restrict__ x,
                                const float* __restrict__ gamma,
                                const float* __restrict__ beta,
                                float* __restrict__ scale,
                                float* __restrict__ shift)
{
    const int c = blockIdx.x;
    float s = 0.f, q = 0.f;
    for (int b = 0; b < BB; ++b) {
        const float4* p = (const float4*)(x + ((long)b*40 + c)*HW);
        for (int i = threadIdx.x; i < HW/4; i += blockDim.x) {
            float4 v = __ldg(&p[i]);
            s += v.x + v.y + v.z + v.w;
            q += v.x*v.x + v.y*v.y + v.z*v.z + v.w*v.w;
        }
    }
    __shared__ float ss[32], sq[32];
    #pragma unroll
    for (int o = 16; o; o >>= 1) {
        s += __shfl_xor_sync(~0u, s, o);
        q += __shfl_xor_sync(~0u, q, o);
    }
    int lane = threadIdx.x & 31, w = threadIdx.x >> 5;
    if (!lane) { ss[w] = s; sq[w] = q; }
    __syncthreads();
    if (threadIdx.x < 32) {
        int nw = blockDim.x >> 5;
        s = (threadIdx.x < nw) ? ss[threadIdx.x] : 0.f;
        q = (threadIdx.x < nw) ? sq[threadIdx.x] : 0.f;
        #pragma unroll
        for (int o = 16; o; o >>= 1) {
            s += __shfl_xor_sync(~0u, s, o);
            q += __shfl_xor_sync(~0u, q, o);
        }
        if (threadIdx.x == 0) {
            const float N = (float)(BB*HW);
            float m  = s / N;
            float v  = q / N - m*m;
            float sc = gamma[c] * rsqrtf(v + 1e-5f);
            scale[c] = sc;
            shift[c] = beta[c] - m*sc;
        }
    }
}

// ---------------------------------------------------------------------------
// Host driver
// ---------------------------------------------------------------------------
extern "C" void kernel_launch(void* const* d_in, const int* in_sizes, int n_in,
                              void* d_out, int out_size)
{
    const float* x1  = (const float*)d_in[0];
    const float* x2  = (const float*)d_in[1];
    const float* Wf  = (const float*)d_in[2];
    const float* bf  = (const float*)d_in[3];
    const float* Wi  = (const float*)d_in[4];
    const float* bi  = (const float*)d_in[5];
    const float* Wc  = (const float*)d_in[6];
    const float* bc  = (const float*)d_in[7];
    const float* Wq  = (const float*)d_in[8];
    const float* bq  = (const float*)d_in[9];
    const float* W0  = (const float*)d_in[10];
    const float* g0  = (const float*)d_in[11];
    const float* be0 = (const float*)d_in[12];
    const float* W1  = (const float*)d_in[13];
    const float* g1  = (const float*)d_in[14];
    const float* be1 = (const float*)d_in[15];
    const float* W2  = (const float*)d_in[16];
    const float* b2w = (const float*)d_in[17];
    const float* Wh  = (const float*)d_in[18];
    const float* bh  = (const float*)d_in[19];
    float* out = (float*)d_out;

    float *ph, *pc, *pr, *pg, *px0, *px1, *pWg, *pbg, *pWh2, *pbh2;
    float *psc0, *psh0, *psc1, *psh1;
    cudaGetSymbolAddress((void**)&ph,   g_h);
    cudaGetSymbolAddress((void**)&pc,   g_c);
    cudaGetSymbolAddress((void**)&pr,   g_r);
    cudaGetSymbolAddress((void**)&pg,   g_gate);
    cudaGetSymbolAddress((void**)&px0,  g_x0);
    cudaGetSymbolAddress((void**)&px1,  g_x1);
    cudaGetSymbolAddress((void**)&pWg,  g_Wg);
    cudaGetSymbolAddress((void**)&pbg,  g_bg);
    cudaGetSymbolAddress((void**)&pWh2, g_Wh2);
    cudaGetSymbolAddress((void**)&pbh2, g_bh2);
    cudaGetSymbolAddress((void**)&psc0, g_sc0);
    cudaGetSymbolAddress((void**)&psh0, g_sh0);
    cudaGetSymbolAddress((void**)&psc1, g_sc1);
    cudaGetSymbolAddress((void**)&psh1, g_sh1);

    zero_state_kernel<<<(BB*8*HW + 255)/256, 256>>>();
    prep_weights_kernel<<<(56*40*9 + 255)/256, 256>>>(Wf, bf, Wi, bi, Wc, bc, Wq, bq,
                                                      Wh, bh, W2, b2w);

    const long O2_OFF = (long)BB*3*DD*HW;   // o1 tensor size

    for (int t = 0; t < DD; ++t) {
        for (int phase = 0; phase < 2; ++phase) {
            const float* xin   = (phase ? x2 : x1) + (long)t*32*HW;
            float*       obase = out + (phase ? O2_OFF : 0);

            // gate conv: concat(x[32], h[8]) -> 56 raw gates
            conv_kernel<3, 56, 0><<<dim3(6, 6, BB*7), 256>>>(
                xin, (long)DD*32*HW, ph, (long)8*HW, 32,
                pWg, pbg, nullptr, nullptr, pg, nullptr, 0);

            // LSTM pointwise: update c, build r = [c', sig(q)]
            lstm_update_kernel<<<(BB*HW + 255)/256, 256>>>(pg, pc, pr);

            // conv0: 5x5 r -> raw x0
            conv_kernel<5, 40, 0><<<dim3(6, 6, BB*5), 256>>>(
                pr, (long)40*HW, nullptr, 0, 40,
                W0, nullptr, nullptr, nullptr, px0, nullptr, 0);
            bn_stats_kernel<<<40, 512>>>(px0, g0, be0, psc0, psh0);

            // conv1: 5x5 relu(bn0(x0)) -> raw x1
            conv_kernel<5, 40, 0><<<dim3(6, 6, BB*5), 256>>>(
                px0, (long)40*HW, nullptr, 0, 40,
                W1, nullptr, psc0, psh0, px1, nullptr, 0);
            bn_stats_kernel<<<40, 512>>>(px1, g1, be1, psc1, psh1);

            // head: 5x5 relu(bn1(x1)) -> h (oc 0-7) + depth out (oc 8-10)
            conv_kernel<5, 11, 1><<<dim3(6, 6, BB*2), 256>>>(
                px1, (long)40*HW, nullptr, 0, 40,
                pWh2, pbh2, psc1, psh1, ph, obase, t);
        }
    }
}

// round 6
// speedup vs baseline: 1.1229x; 1.1229x over previous
#include <cuda_runtime.h>
#include <math.h>

// ---------------------------------------------------------------------------
// Problem constants
// ---------------------------------------------------------------------------
#define HH 192
#define WW 192
#define HW (192*192)
#define BB 4
#define DD 8
#define ICT 40          // conv input channels (always 40 = NF + 8)
#define TILE 32

// ---------------------------------------------------------------------------
// Scratch (device globals — no allocation allowed)
// ---------------------------------------------------------------------------
__device__ float g_h   [BB*8 *HW];   // h state
__device__ float g_c   [BB*8 *HW];   // c state
__device__ float g_r   [BB*40*HW];   // r = [cs, sigmoid(q)]
__device__ float g_gate[BB*56*HW];   // raw gate conv output
__device__ float g_x0  [BB*40*HW];   // raw conv0 output
__device__ float g_x1  [BB*40*HW];   // raw conv1 output
__device__ float g_Wg  [56*40*3*3];  // packed gate weights [oc][ic][ky][kx]
__device__ float g_bg  [56];
__device__ float g_Wh2 [11*40*5*5];  // packed head weights (Wh padded to 5x5 | W2)
__device__ float g_bh2 [11];
__device__ float g_sc0[40], g_sh0[40], g_sc1[40], g_sh1[40];  // BN scale/shift

__device__ __forceinline__ float sigmoidf_(float x) { return 1.f / (1.f + expf(-x)); }

// ---- packed f32x2 helpers (sm_103a: full-width fp32 pipe only via f32x2) ----
__device__ __forceinline__ unsigned long long pack2_(float a, float b) {
    unsigned long long r;
    asm("mov.b64 %0, {%1, %2};" : "=l"(r) : "f"(a), "f"(b));
    return r;
}
__device__ __forceinline__ unsigned long long dup2_(float a) {
    unsigned long long r;
    asm("mov.b64 %0, {%1, %1};" : "=l"(r) : "f"(a));
    return r;
}
__device__ __forceinline__ void fma2_(unsigned long long &acc,
                                      unsigned long long a,
                                      unsigned long long b) {
    asm("fma.rn.f32x2 %0, %1, %2, %0;" : "+l"(acc) : "l"(a), "l"(b));
}
__device__ __forceinline__ float2 unpack2_(unsigned long long v) {
    float2 f;
    asm("mov.b64 {%0, %1}, %2;" : "=f"(f.x), "=f"(f.y) : "l"(v));
    return f;
}

// ---------------------------------------------------------------------------
// Zero the recurrent state
// ---------------------------------------------------------------------------
__global__ void zero_state_kernel() {
    int i = blockIdx.x * blockDim.x + threadIdx.x;
    if (i < BB*8*HW) { g_h[i] = 0.f; g_c[i] = 0.f; }
}

// ---------------------------------------------------------------------------
// Pack weights: gates (Wf|Wi|Wc|Wq -> 56 oc) and head (Wh centered in 5x5 | W2)
// ---------------------------------------------------------------------------
__global__ void prep_weights_kernel(
    const float* __restrict__ Wf, const float* __restrict__ bf,
    const float* __restrict__ Wi, const float* __restrict__ bi,
    const float* __restrict__ Wc, const float* __restrict__ bc,
    const float* __restrict__ Wq, const float* __restrict__ bq,
    const float* __restrict__ Wh, const float* __restrict__ bh,
    const float* __restrict__ W2, const float* __restrict__ b2)
{
    int i = blockIdx.x * blockDim.x + threadIdx.x;
    const int NG = 56*40*9;
    if (i < NG) {
        int oc = i / 360, r = i % 360;
        float v;
        if      (oc < 8 ) v = Wf[ oc     *360 + r];
        else if (oc < 16) v = Wi[(oc-8 ) *360 + r];
        else if (oc < 24) v = Wc[(oc-16) *360 + r];
        else              v = Wq[(oc-24) *360 + r];
        g_Wg[i] = v;
    }
    if (i < 56) {
        g_bg[i] = (i < 8) ? bf[i] : (i < 16) ? bi[i-8] : (i < 24) ? bc[i-16] : bq[i-24];
    }
    const int NH = 11*40*25;
    if (i < NH) {
        int oc = i / 1000, r = i % 1000, c = r / 25, k = r % 25, ky = k / 5, kx = k % 5;
        float v = 0.f;
        if (oc < 8) {
            if (ky >= 1 && ky <= 3 && kx >= 1 && kx <= 3)
                v = Wh[((oc*40 + c)*3 + (ky-1))*3 + (kx-1)];
        } else {
            v = W2[(((oc-8)*40 + c)*5 + ky)*5 + kx];
        }
        g_Wh2[i] = v;
    }
    if (i < 11) g_bh2[i] = (i < 8) ? bh[i] : b2[i-8];
}

// ---------------------------------------------------------------------------
// Generic direct conv, f32x2-packed inner loop.
//  K      : kernel size (3 or 5), pad = K/2
//  OCT    : total output channels
//  MODE   : 0 = store raw to out (B,OCT,H,W)
//           1 = head: oc<8 -> out (h state, B,8,H,W); oc in [8,11) -> out_o
//               at ((b*3+(oc-8))*DD + t)*HW + pix
//  Input: channels [0,c_split) from in1 (batch stride bs1),
//         channels [c_split,40) from in2 (batch stride bs2).
//  Optional per-channel input transform:  v = max(v*isc[c]+ish[c], 0)  (BN+ReLU)
//  Tiling: 32x32 output pixels, 8 oc per block, 256 threads,
//          each thread: 4 pixels (y strided by 8) x 4 oc-PAIRS (f32x2).
// ---------------------------------------------------------------------------
template<int K, int OCT, int MODE>
__global__ __launch_bounds__(256, 2)
void conv_kernel(
    const float* __restrict__ in1, long bs1,
    const float* __restrict__ in2, long bs2, int c_split,
    const float* __restrict__ Wt,  const float* __restrict__ bias,
    const float* __restrict__ isc, const float* __restrict__ ish,
    float* __restrict__ out, float* __restrict__ out_o, int t)
{
    constexpr int PS  = TILE + K - 1;
    constexpr int PAD = K / 2;
    constexpr int NGROUP = (OCT + 7) / 8;

    __shared__ __align__(16) float patch[8 * PS * PS];
    __shared__ __align__(16) float wts  [8 * K * K * 8];

    const int b   = blockIdx.z / NGROUP;
    const int g   = blockIdx.z % NGROUP;
    const int tx0 = blockIdx.x * TILE;
    const int ty0 = blockIdx.y * TILE;
    const int tid = threadIdx.x;
    const int x   = tid & 31;
    const int y0  = tid >> 5;          // 0..7

    // acc2[p][j] holds outputs for oc pair (g*8+2j, g*8+2j+1) at pixel p
    unsigned long long acc2[4][4];
    #pragma unroll
    for (int j = 0; j < 4; ++j) {
        int oc0 = g*8 + 2*j;
        float b0 = (bias != nullptr && oc0   < OCT) ? __ldg(&bias[oc0  ]) : 0.f;
        float b1 = (bias != nullptr && oc0+1 < OCT) ? __ldg(&bias[oc0+1]) : 0.f;
        unsigned long long bp = pack2_(b0, b1);
        #pragma unroll
        for (int p = 0; p < 4; ++p) acc2[p][j] = bp;
    }

    for (int chunk = 0; chunk < 5; ++chunk) {
        __syncthreads();
        // ---- load input patch (8 channels) ----
        for (int idx = tid; idx < 8*PS*PS; idx += 256) {
            int c  = idx / (PS*PS);
            int r  = idx - c*PS*PS;
            int yy = r / PS, xx = r - yy*PS;
            int gy = ty0 + yy - PAD, gx = tx0 + xx - PAD;
            float v = 0.f;
            if ((unsigned)gy < HH && (unsigned)gx < WW) {
                int cg = chunk*8 + c;
                const float* src; int cc;
                if (cg < c_split) { src = in1 + (long)b*bs1; cc = cg; }
                else              { src = in2 + (long)b*bs2; cc = cg - c_split; }
                v = __ldg(src + (long)cc*HW + gy*WW + gx);
                if (isc != nullptr) v = fmaxf(v * isc[cg] + ish[cg], 0.f);
            }
            patch[idx] = v;
        }
        // ---- load weight chunk: layout ((c*K+ky)*K+kx)*8 + oc ----
        for (int idx = tid; idx < 8*K*K*8; idx += 256) {
            int oc   = idx & 7;
            int rest = idx >> 3;
            int kx = rest % K; rest /= K;
            int ky = rest % K;
            int c  = rest / K;
            int ocg = g*8 + oc;
            float wv = 0.f;
            if (ocg < OCT)
                wv = __ldg(&Wt[((long)ocg*ICT + chunk*8 + c)*K*K + ky*K + kx]);
            wts[idx] = wv;
        }
        __syncthreads();
        // ---- compute (f32x2 packed: 2 MACs per FMA instruction) ----
        #pragma unroll 1
        for (int c = 0; c < 8; ++c) {
            const float* pc_ = &patch[c*PS*PS];
            #pragma unroll
            for (int ky = 0; ky < K; ++ky) {
                #pragma unroll
                for (int kx = 0; kx < K; ++kx) {
                    const unsigned long long* wp =
                        (const unsigned long long*)&wts[((c*K + ky)*K + kx)*8];
                    unsigned long long w0 = wp[0], w1 = wp[1],
                                       w2 = wp[2], w3 = wp[3];
                    #pragma unroll
                    for (int p = 0; p < 4; ++p) {
                        unsigned long long iv2 =
                            dup2_(pc_[(y0 + p*8 + ky)*PS + x + kx]);
                        fma2_(acc2[p][0], iv2, w0);
                        fma2_(acc2[p][1], iv2, w1);
                        fma2_(acc2[p][2], iv2, w2);
                        fma2_(acc2[p][3], iv2, w3);
                    }
                }
            }
        }
    }

    // ---- store ----
    #pragma unroll
    for (int p = 0; p < 4; ++p) {
        int y   = ty0 + y0 + p*8;
        int pix = y*WW + tx0 + x;
        #pragma unroll
        for (int j = 0; j < 4; ++j) {
            float2 v2 = unpack2_(acc2[p][j]);
            #pragma unroll
            for (int h = 0; h < 2; ++h) {
                int oc = g*8 + 2*j + h;
                if (oc >= OCT) continue;
                float v = (h == 0) ? v2.x : v2.y;
                if (MODE == 0) {
                    out[((long)b*OCT + oc)*HW + pix] = v;
                } else {
                    if (oc < 8) out[((long)b*8 + oc)*HW + pix] = v;
                    else        out_o[(((long)b*3 + (oc-8))*DD + t)*HW + pix] = v;
                }
            }
        }
    }
}

// ---------------------------------------------------------------------------
// LSTM pointwise update:
//  f,i,g,q from raw gates; c' = sig(f)*c + sig(i)*tanh(g);
//  r[0:8]=c', r[8:40]=sig(q)
// ---------------------------------------------------------------------------
__global__ void lstm_update_kernel(const float* __restrict__ gates,
                                   float* __restrict__ cbuf,
                                   float* __restrict__ rbuf)
{
    int i = blockIdx.x * blockDim.x + threadIdx.x;
    if (i >= BB*HW) return;
    int b = i / HW, p = i - b*HW;
    const float* G = gates + (long)b*56*HW + p;
    float*       C = cbuf  + (long)b*8 *HW + p;
    float*       R = rbuf  + (long)b*40*HW + p;
    #pragma unroll
    for (int c = 0; c < 8; ++c) {
        float f  = sigmoidf_(G[(c     )*HW]);
        float ii = sigmoidf_(G[(c + 8 )*HW]);
        float gg = tanhf    (G[(c + 16)*HW]);
        float cs = f * C[c*HW] + ii * gg;
        C[c*HW] = cs;
        R[c*HW] = cs;
    }
    #pragma unroll
    for (int c = 0; c < 32; ++c)
        R[(8 + c)*HW] = sigmoidf_(G[(24 + c)*HW]);
}

// ---------------------------------------------------------------------------
// Deterministic training-mode BN stats: one block per channel.
// Produces scale = gamma*rsqrt(var+eps), shift = beta - mean*scale.
// ---------------------------------------------------------------------------
__global__ void bn_stats_kernel(const float* __restrict__ x,
                                const float* __restrict__ gamma,
                                const float* __restrict__ beta,
                                float* __restrict__ scale,
                                float* __restrict__ shift)
{
    const int c = blockIdx.x;
    float s = 0.f, q = 0.f;
    for (int b = 0; b < BB; ++b) {
        const float4* p = (const float4*)(x + ((long)b*40 + c)*HW);
        for (int i = threadIdx.x; i < HW/4; i += blockDim.x) {
            float4 v = __ldg(&p[i]);
            s += v.x + v.y + v.z + v.w;
            q += v.x*v.x + v.y*v.y + v.z*v.z + v.w*v.w;
        }
    }
    __shared__ float ss[32], sq[32];
    #pragma unroll
    for (int o = 16; o; o >>= 1) {
        s += __shfl_xor_sync(~0u, s, o);
        q += __shfl_xor_sync(~0u, q, o);
    }
    int lane = threadIdx.x & 31, w = threadIdx.x >> 5;
    if (!lane) { ss[w] = s; sq[w] = q; }
    __syncthreads();
    if (threadIdx.x < 32) {
        int nw = blockDim.x >> 5;
        s = (threadIdx.x < nw) ? ss[threadIdx.x] : 0.f;
        q = (threadIdx.x < nw) ? sq[threadIdx.x] : 0.f;
        #pragma unroll
        for (int o = 16; o; o >>= 1) {
            s += __shfl_xor_sync(~0u, s, o);
            q += __shfl_xor_sync(~0u, q, o);
        }
        if (threadIdx.x == 0) {
            const float N = (float)(BB*HW);
            float m  = s / N;
            float v  = q / N - m*m;
            float sc = gamma[c] * rsqrtf(v + 1e-5f);
            scale[c] = sc;
            shift[c] = beta[c] - m*sc;
        }
    }
}

// ---------------------------------------------------------------------------
// Host driver
// ---------------------------------------------------------------------------
extern "C" void kernel_launch(void* const* d_in, const int* in_sizes, int n_in,
                              void* d_out, int out_size)
{
    const float* x1  = (const float*)d_in[0];
    const float* x2  = (const float*)d_in[1];
    const float* Wf  = (const float*)d_in[2];
    const float* bf  = (const float*)d_in[3];
    const float* Wi  = (const float*)d_in[4];
    const float* bi  = (const float*)d_in[5];
    const float* Wc  = (const float*)d_in[6];
    const float* bc  = (const float*)d_in[7];
    const float* Wq  = (const float*)d_in[8];
    const float* bq  = (const float*)d_in[9];
    const float* W0  = (const float*)d_in[10];
    const float* g0  = (const float*)d_in[11];
    const float* be0 = (const float*)d_in[12];
    const float* W1  = (const float*)d_in[13];
    const float* g1  = (const float*)d_in[14];
    const float* be1 = (const float*)d_in[15];
    const float* W2  = (const float*)d_in[16];
    const float* b2w = (const float*)d_in[17];
    const float* Wh  = (const float*)d_in[18];
    const float* bh  = (const float*)d_in[19];
    float* out = (float*)d_out;

    float *ph, *pc, *pr, *pg, *px0, *px1, *pWg, *pbg, *pWh2, *pbh2;
    float *psc0, *psh0, *psc1, *psh1;
    cudaGetSymbolAddress((void**)&ph,   g_h);
    cudaGetSymbolAddress((void**)&pc,   g_c);
    cudaGetSymbolAddress((void**)&pr,   g_r);
    cudaGetSymbolAddress((void**)&pg,   g_gate);
    cudaGetSymbolAddress((void**)&px0,  g_x0);
    cudaGetSymbolAddress((void**)&px1,  g_x1);
    cudaGetSymbolAddress((void**)&pWg,  g_Wg);
    cudaGetSymbolAddress((void**)&pbg,  g_bg);
    cudaGetSymbolAddress((void**)&pWh2, g_Wh2);
    cudaGetSymbolAddress((void**)&pbh2, g_bh2);
    cudaGetSymbolAddress((void**)&psc0, g_sc0);
    cudaGetSymbolAddress((void**)&psh0, g_sh0);
    cudaGetSymbolAddress((void**)&psc1, g_sc1);
    cudaGetSymbolAddress((void**)&psh1, g_sh1);

    zero_state_kernel<<<(BB*8*HW + 255)/256, 256>>>();
    prep_weights_kernel<<<(56*40*9 + 255)/256, 256>>>(Wf, bf, Wi, bi, Wc, bc, Wq, bq,
                                                      Wh, bh, W2, b2w);

    const long O2_OFF = (long)BB*3*DD*HW;   // o1 tensor size

    for (int t = 0; t < DD; ++t) {
        for (int phase = 0; phase < 2; ++phase) {
            const float* xin   = (phase ? x2 : x1) + (long)t*32*HW;
            float*       obase = out + (phase ? O2_OFF : 0);

            // gate conv: concat(x[32], h[8]) -> 56 raw gates
            conv_kernel<3, 56, 0><<<dim3(6, 6, BB*7), 256>>>(
                xin, (long)DD*32*HW, ph, (long)8*HW, 32,
                pWg, pbg, nullptr, nullptr, pg, nullptr, 0);

            // LSTM pointwise: update c, build r = [c', sig(q)]
            lstm_update_kernel<<<(BB*HW + 255)/256, 256>>>(pg, pc, pr);

            // conv0: 5x5 r -> raw x0
            conv_kernel<5, 40, 0><<<dim3(6, 6, BB*5), 256>>>(
                pr, (long)40*HW, nullptr, 0, 40,
                W0, nullptr, nullptr, nullptr, px0, nullptr, 0);
            bn_stats_kernel<<<40, 512>>>(px0, g0, be0, psc0, psh0);

            // conv1: 5x5 relu(bn0(x0)) -> raw x1
            conv_kernel<5, 40, 0><<<dim3(6, 6, BB*5), 256>>>(
                px0, (long)40*HW, nullptr, 0, 40,
                W1, nullptr, psc0, psh0, px1, nullptr, 0);
            bn_stats_kernel<<<40, 512>>>(px1, g1, be1, psc1, psh1);

            // head: 5x5 relu(bn1(x1)) -> h (oc 0-7) + depth out (oc 8-10)
            conv_kernel<5, 11, 1><<<dim3(6, 6, BB*2), 256>>>(
                px1, (long)40*HW, nullptr, 0, 40,
                pWh2, pbh2, psc1, psh1, ph, obase, t);
        }
    }
}

// round 8
// speedup vs baseline: 1.1268x; 1.0035x over previous
#include <cuda_runtime.h>
#include <math.h>

// ---------------------------------------------------------------------------
// Problem constants
// ---------------------------------------------------------------------------
#define HH 192
#define WW 192
#define HW (192*192)
#define BB 4
#define DD 8
#define ICT 40          // conv input channels (always 40 = NF + 8)
#define TILE 32

// ---------------------------------------------------------------------------
// Scratch (device globals — no allocation allowed)
// ---------------------------------------------------------------------------
__device__ float g_h   [BB*8 *HW];   // h state
__device__ float g_c   [BB*8 *HW];   // c state
__device__ float g_r   [BB*40*HW];   // r = [cs, sigmoid(q)]
__device__ float g_gate[BB*56*HW];   // raw gate conv output
__device__ float g_x0  [BB*40*HW];   // raw conv0 output
__device__ float g_x1  [BB*40*HW];   // raw conv1 output
__device__ float g_Wg  [56*40*3*3];  // packed gate weights [oc][ic][ky][kx]
__device__ float g_bg  [56];
__device__ float g_Wh2 [11*40*5*5];  // packed head weights (Wh padded to 5x5 | W2)
__device__ float g_bh2 [11];
__device__ float g_sc0[40], g_sh0[40], g_sc1[40], g_sh1[40];  // BN scale/shift

__device__ __forceinline__ float sigmoidf_(float x) { return 1.f / (1.f + expf(-x)); }

// ---- packed f32x2 helpers (sm_103a: full-width fp32 pipe only via f32x2) ----
__device__ __forceinline__ unsigned long long pack2_(float a, float b) {
    unsigned long long r;
    asm("mov.b64 %0, {%1, %2};" : "=l"(r) : "f"(a), "f"(b));
    return r;
}
__device__ __forceinline__ unsigned long long dup2_(float a) {
    unsigned long long r;
    asm("mov.b64 %0, {%1, %1};" : "=l"(r) : "f"(a));
    return r;
}
__device__ __forceinline__ void fma2_(unsigned long long &acc,
                                      unsigned long long a,
                                      unsigned long long b) {
    asm("fma.rn.f32x2 %0, %1, %2, %0;" : "+l"(acc) : "l"(a), "l"(b));
}
__device__ __forceinline__ float2 unpack2_(unsigned long long v) {
    float2 f;
    asm("mov.b64 {%0, %1}, %2;" : "=f"(f.x), "=f"(f.y) : "l"(v));
    return f;
}

// ---------------------------------------------------------------------------
// Zero the recurrent state
// ---------------------------------------------------------------------------
__global__ void zero_state_kernel() {
    int i = blockIdx.x * blockDim.x + threadIdx.x;
    if (i < BB*8*HW) { g_h[i] = 0.f; g_c[i] = 0.f; }
}

// ---------------------------------------------------------------------------
// Pack weights: gates (Wf|Wi|Wc|Wq -> 56 oc) and head (Wh centered in 5x5 | W2)
// ---------------------------------------------------------------------------
__global__ void prep_weights_kernel(
    const float* __restrict__ Wf, const float* __restrict__ bf,
    const float* __restrict__ Wi, const float* __restrict__ bi,
    const float* __restrict__ Wc, const float* __restrict__ bc,
    const float* __restrict__ Wq, const float* __restrict__ bq,
    const float* __restrict__ Wh, const float* __restrict__ bh,
    const float* __restrict__ W2, const float* __restrict__ b2)
{
    int i = blockIdx.x * blockDim.x + threadIdx.x;
    const int NG = 56*40*9;
    if (i < NG) {
        int oc = i / 360, r = i % 360;
        float v;
        if      (oc < 8 ) v = Wf[ oc     *360 + r];
        else if (oc < 16) v = Wi[(oc-8 ) *360 + r];
        else if (oc < 24) v = Wc[(oc-16) *360 + r];
        else              v = Wq[(oc-24) *360 + r];
        g_Wg[i] = v;
    }
    if (i < 56) {
        g_bg[i] = (i < 8) ? bf[i] : (i < 16) ? bi[i-8] : (i < 24) ? bc[i-16] : bq[i-24];
    }
    const int NH = 11*40*25;
    if (i < NH) {
        int oc = i / 1000, r = i % 1000, c = r / 25, k = r % 25, ky = k / 5, kx = k % 5;
        float v = 0.f;
        if (oc < 8) {
            if (ky >= 1 && ky <= 3 && kx >= 1 && kx <= 3)
                v = Wh[((oc*40 + c)*3 + (ky-1))*3 + (kx-1)];
        } else {
            v = W2[(((oc-8)*40 + c)*5 + ky)*5 + kx];
        }
        g_Wh2[i] = v;
    }
    if (i < 11) g_bh2[i] = (i < 8) ? bh[i] : b2[i-8];
}

// ---------------------------------------------------------------------------
// Generic direct conv, f32x2-packed inner loop.
//  K      : kernel size (3 or 5), pad = K/2
//  OCT    : total output channels
//  MODE   : 0 = store raw to out (B,OCT,H,W)
//           1 = head: oc<8 -> out (h state, B,8,H,W); oc in [8,11) -> out_o
//               at ((b*3+(oc-8))*DD + t)*HW + pix
//  Input: channels [0,c_split) from in1 (batch stride bs1),
//         channels [c_split,40) from in2 (batch stride bs2).
//  Optional per-channel input transform:  v = max(v*isc[c]+ish[c], 0)  (BN+ReLU)
//  Tiling: 32x32 output pixels, 8 oc per block, 256 threads,
//          each thread: 4 pixels (y strided by 8) x 4 oc-PAIRS (f32x2).
// ---------------------------------------------------------------------------
template<int K, int OCT, int MODE>
__global__ __launch_bounds__(256, 2)
void conv_kernel(
    const float* __restrict__ in1, long bs1,
    const float* __restrict__ in2, long bs2, int c_split,
    const float* __restrict__ Wt,  const float* __restrict__ bias,
    const float* __restrict__ isc, const float* __restrict__ ish,
    float* __restrict__ out, float* __restrict__ out_o, int t)
{
    constexpr int PS  = TILE + K - 1;
    constexpr int PAD = K / 2;
    constexpr int NGROUP = (OCT + 7) / 8;

    __shared__ __align__(16) float patch[8 * PS * PS];
    __shared__ __align__(16) float wts  [8 * K * K * 8];

    const int b   = blockIdx.z / NGROUP;
    const int g   = blockIdx.z % NGROUP;
    const int tx0 = blockIdx.x * TILE;
    const int ty0 = blockIdx.y * TILE;
    const int tid = threadIdx.x;
    const int x   = tid & 31;
    const int y0  = tid >> 5;          // 0..7

    // acc2[p][j] holds outputs for oc pair (g*8+2j, g*8+2j+1) at pixel p
    unsigned long long acc2[4][4];
    #pragma unroll
    for (int j = 0; j < 4; ++j) {
        int oc0 = g*8 + 2*j;
        float b0 = (bias != nullptr && oc0   < OCT) ? __ldg(&bias[oc0  ]) : 0.f;
        float b1 = (bias != nullptr && oc0+1 < OCT) ? __ldg(&bias[oc0+1]) : 0.f;
        unsigned long long bp = pack2_(b0, b1);
        #pragma unroll
        for (int p = 0; p < 4; ++p) acc2[p][j] = bp;
    }

    for (int chunk = 0; chunk < 5; ++chunk) {
        __syncthreads();
        // ---- load input patch (8 channels) ----
        for (int idx = tid; idx < 8*PS*PS; idx += 256) {
            int c  = idx / (PS*PS);
            int r  = idx - c*PS*PS;
            int yy = r / PS, xx = r - yy*PS;
            int gy = ty0 + yy - PAD, gx = tx0 + xx - PAD;
            float v = 0.f;
            if ((unsigned)gy < HH && (unsigned)gx < WW) {
                int cg = chunk*8 + c;
                const float* src; int cc;
                if (cg < c_split) { src = in1 + (long)b*bs1; cc = cg; }
                else              { src = in2 + (long)b*bs2; cc = cg - c_split; }
                v = __ldg(src + (long)cc*HW + gy*WW + gx);
                if (isc != nullptr) v = fmaxf(v * isc[cg] + ish[cg], 0.f);
            }
            patch[idx] = v;
        }
        // ---- load weight chunk: layout ((c*K+ky)*K+kx)*8 + oc ----
        for (int idx = tid; idx < 8*K*K*8; idx += 256) {
            int oc   = idx & 7;
            int rest = idx >> 3;
            int kx = rest % K; rest /= K;
            int ky = rest % K;
            int c  = rest / K;
            int ocg = g*8 + oc;
            float wv = 0.f;
            if (ocg < OCT)
                wv = __ldg(&Wt[((long)ocg*ICT + chunk*8 + c)*K*K + ky*K + kx]);
            wts[idx] = wv;
        }
        __syncthreads();
        // ---- compute (f32x2 packed: 2 MACs per FMA instruction) ----
        #pragma unroll 1
        for (int c = 0; c < 8; ++c) {
            const float* pc_ = &patch[c*PS*PS];
            #pragma unroll
            for (int ky = 0; ky < K; ++ky) {
                #pragma unroll
                for (int kx = 0; kx < K; ++kx) {
                    const unsigned long long* wp =
                        (const unsigned long long*)&wts[((c*K + ky)*K + kx)*8];
                    unsigned long long w0 = wp[0], w1 = wp[1],
                                       w2 = wp[2], w3 = wp[3];
                    #pragma unroll
                    for (int p = 0; p < 4; ++p) {
                        unsigned long long iv2 =
                            dup2_(pc_[(y0 + p*8 + ky)*PS + x + kx]);
                        fma2_(acc2[p][0], iv2, w0);
                        fma2_(acc2[p][1], iv2, w1);
                        fma2_(acc2[p][2], iv2, w2);
                        fma2_(acc2[p][3], iv2, w3);
                    }
                }
            }
        }
    }

    // ---- store ----
    #pragma unroll
    for (int p = 0; p < 4; ++p) {
        int y   = ty0 + y0 + p*8;
        int pix = y*WW + tx0 + x;
        #pragma unroll
        for (int j = 0; j < 4; ++j) {
            float2 v2 = unpack2_(acc2[p][j]);
            #pragma unroll
            for (int h = 0; h < 2; ++h) {
                int oc = g*8 + 2*j + h;
                if (oc >= OCT) continue;
                float v = (h == 0) ? v2.x : v2.y;
                if (MODE == 0) {
                    out[((long)b*OCT + oc)*HW + pix] = v;
                } else {
                    if (oc < 8) out[((long)b*8 + oc)*HW + pix] = v;
                    else        out_o[(((long)b*3 + (oc-8))*DD + t)*HW + pix] = v;
                }
            }
        }
    }
}

// ---------------------------------------------------------------------------
// LSTM pointwise update:
//  f,i,g,q from raw gates; c' = sig(f)*c + sig(i)*tanh(g);
//  r[0:8]=c', r[8:40]=sig(q)
// ---------------------------------------------------------------------------
__global__ void lstm_update_kernel(const float* __restrict__ gates,
                                   float* __restrict__ cbuf,
                                   float* __restrict__ rbuf)
{
    int i = blockIdx.x * blockDim.x + threadIdx.x;
    if (i >= BB*HW) return;
    int b = i / HW, p = i - b*HW;
    const float* G = gates + (long)b*56*HW + p;
    float*       C = cbuf  + (long)b*8 *HW + p;
    float*       R = rbuf  + (long)b*40*HW + p;
    #pragma unroll
    for (int c = 0; c < 8; ++c) {
        float f  = sigmoidf_(G[(c     )*HW]);
        float ii = sigmoidf_(G[(c + 8 )*HW]);
        float gg = tanhf    (G[(c + 16)*HW]);
        float cs = f * C[c*HW] + ii * gg;
        C[c*HW] = cs;
        R[c*HW] = cs;
    }
    #pragma unroll
    for (int c = 0; c < 32; ++c)
        R[(8 + c)*HW] = sigmoidf_(G[(24 + c)*HW]);
}

// ---------------------------------------------------------------------------
// Deterministic training-mode BN stats: one block per channel.
// Produces scale = gamma*rsqrt(var+eps), shift = beta - mean*scale.
// ---------------------------------------------------------------------------
__global__ void bn_stats_kernel(const float* __restrict__ x,
                                const float* __restrict__ gamma,
                                const float* __restrict__ beta,
                                float* __restrict__ scale,
                                float* __restrict__ shift)
{
    const int c = blockIdx.x;
    float s = 0.f, q = 0.f;
    for (int b = 0; b < BB; ++b) {
        const float4* p = (const float4*)(x + ((long)b*40 + c)*HW);
        for (int i = threadIdx.x; i < HW/4; i += blockDim.x) {
            float4 v = __ldg(&p[i]);
            s += v.x + v.y + v.z + v.w;
            q += v.x*v.x + v.y*v.y + v.z*v.z + v.w*v.w;
        }
    }
    __shared__ float ss[32], sq[32];
    #pragma unroll
    for (int o = 16; o; o >>= 1) {
        s += __shfl_xor_sync(~0u, s, o);
        q += __shfl_xor_sync(~0u, q, o);
    }
    int lane = threadIdx.x & 31, w = threadIdx.x >> 5;
    if (!lane) { ss[w] = s; sq[w] = q; }
    __syncthreads();
    if (threadIdx.x < 32) {
        int nw = blockDim.x >> 5;
        s = (threadIdx.x < nw) ? ss[threadIdx.x] : 0.f;
        q = (threadIdx.x < nw) ? sq[threadIdx.x] : 0.f;
        #pragma unroll
        for (int o = 16; o; o >>= 1) {
            s += __shfl_xor_sync(~0u, s, o);
            q += __shfl_xor_sync(~0u, q, o);
        }
        if (threadIdx.x == 0) {
            const float N = (float)(BB*HW);
            float m  = s / N;
            float v  = q / N - m*m;
            float sc = gamma[c] * rsqrtf(v + 1e-5f);
            scale[c] = sc;
            shift[c] = beta[c] - m*sc;
        }
    }
}

// ---------------------------------------------------------------------------
// Host driver
// ---------------------------------------------------------------------------
extern "C" void kernel_launch(void* const* d_in, const int* in_sizes, int n_in,
                              void* d_out, int out_size)
{
    const float* x1  = (const float*)d_in[0];
    const float* x2  = (const float*)d_in[1];
    const float* Wf  = (const float*)d_in[2];
    const float* bf  = (const float*)d_in[3];
    const float* Wi  = (const float*)d_in[4];
    const float* bi  = (const float*)d_in[5];
    const float* Wc  = (const float*)d_in[6];
    const float* bc  = (const float*)d_in[7];
    const float* Wq  = (const float*)d_in[8];
    const float* bq  = (const float*)d_in[9];
    const float* W0  = (const float*)d_in[10];
    const float* g0  = (const float*)d_in[11];
    const float* be0 = (const float*)d_in[12];
    const float* W1  = (const float*)d_in[13];
    const float* g1  = (const float*)d_in[14];
    const float* be1 = (const float*)d_in[15];
    const float* W2  = (const float*)d_in[16];
    const float* b2w = (const float*)d_in[17];
    const float* Wh  = (const float*)d_in[18];
    const float* bh  = (const float*)d_in[19];
    float* out = (float*)d_out;

    float *ph, *pc, *pr, *pg, *px0, *px1, *pWg, *pbg, *pWh2, *pbh2;
    float *psc0, *psh0, *psc1, *psh1;
    cudaGetSymbolAddress((void**)&ph,   g_h);
    cudaGetSymbolAddress((void**)&pc,   g_c);
    cudaGetSymbolAddress((void**)&pr,   g_r);
    cudaGetSymbolAddress((void**)&pg,   g_gate);
    cudaGetSymbolAddress((void**)&px0,  g_x0);
    cudaGetSymbolAddress((void**)&px1,  g_x1);
    cudaGetSymbolAddress((void**)&pWg,  g_Wg);
    cudaGetSymbolAddress((void**)&pbg,  g_bg);
    cudaGetSymbolAddress((void**)&pWh2, g_Wh2);
    cudaGetSymbolAddress((void**)&pbh2, g_bh2);
    cudaGetSymbolAddress((void**)&psc0, g_sc0);
    cudaGetSymbolAddress((void**)&psh0, g_sh0);
    cudaGetSymbolAddress((void**)&psc1, g_sc1);
    cudaGetSymbolAddress((void**)&psh1, g_sh1);

    zero_state_kernel<<<(BB*8*HW + 255)/256, 256>>>();
    prep_weights_kernel<<<(56*40*9 + 255)/256, 256>>>(Wf, bf, Wi, bi, Wc, bc, Wq, bq,
                                                      Wh, bh, W2, b2w);

    const long O2_OFF = (long)BB*3*DD*HW;   // o1 tensor size

    for (int t = 0; t < DD; ++t) {
        for (int phase = 0; phase < 2; ++phase) {
            const float* xin   = (phase ? x2 : x1) + (long)t*32*HW;
            float*       obase = out + (phase ? O2_OFF : 0);

            // gate conv: concat(x[32], h[8]) -> 56 raw gates
            conv_kernel<3, 56, 0><<<dim3(6, 6, BB*7), 256>>>(
                xin, (long)DD*32*HW, ph, (long)8*HW, 32,
                pWg, pbg, nullptr, nullptr, pg, nullptr, 0);

            // LSTM pointwise: update c, build r = [c', sig(q)]
            lstm_update_kernel<<<(BB*HW + 255)/256, 256>>>(pg, pc, pr);

            // conv0: 5x5 r -> raw x0
            conv_kernel<5, 40, 0><<<dim3(6, 6, BB*5), 256>>>(
                pr, (long)40*HW, nullptr, 0, 40,
                W0, nullptr, nullptr, nullptr, px0, nullptr, 0);
            bn_stats_kernel<<<40, 512>>>(px0, g0, be0, psc0, psh0);

            // conv1: 5x5 relu(bn0(x0)) -> raw x1
            conv_kernel<5, 40, 0><<<dim3(6, 6, BB*5), 256>>>(
                px0, (long)40*HW, nullptr, 0, 40,
                W1, nullptr, psc0, psh0, px1, nullptr, 0);
            bn_stats_kernel<<<40, 512>>>(px1, g1, be1, psc1, psh1);

            // head: 5x5 relu(bn1(x1)) -> h (oc 0-7) + depth out (oc 8-10)
            conv_kernel<5, 11, 1><<<dim3(6, 6, BB*2), 256>>>(
                px1, (long)40*HW, nullptr, 0, 40,
                pWh2, pbh2, psc1, psh1, ph, obase, t);
        }
    }
}

// round 11
// speedup vs baseline: 2.1381x; 1.8974x over previous
#include <cuda_runtime.h>
#include <cuda_bf16.h>
#include <cstdint>
#include <math.h>

#define HH 192
#define WW 192
#define HW (192*192)
#define BB 4
#define DD 8

// ---------------------------------------------------------------------------
// Scratch (device globals — no allocation allowed)
// ---------------------------------------------------------------------------
__device__ float g_h [BB*8*HW];
__device__ float g_c [BB*8*HW];
__device__ float g_x0[BB*40*HW];
__device__ float g_x1[BB*40*HW];
// pixel-major packed bf16 hi/lo: [b][pix][80]  (ch 0..39 hi, 40..79 lo)
__device__ __align__(16) __nv_bfloat16 g_int[(size_t)BB*HW*80];
__device__ __align__(16) __nv_bfloat16 g_rt [(size_t)BB*HW*80];
__device__ __align__(16) __nv_bfloat16 g_x0t[(size_t)BB*HW*80];
__device__ __align__(16) __nv_bfloat16 g_x1t[(size_t)BB*HW*80];

__device__ float g_Wg [56*40*9];    // [oc][ic][tap]
__device__ float g_bg [56];
__device__ float g_Wh2[11*40*25];   // [oc][ic][tap] (Wh centered in 5x5 | W2)
__device__ float g_bh2[16];
__device__ float g_sc0[40], g_sh0[40], g_sc1[40], g_sh1[40];

// plain B operand images: [tap][n][128] bf16 (k: 0-39 Whi, 40-79 Whi, 80-119 Wlo, 120-127 zero)
__device__ __align__(16) __nv_bfloat16 g_Bg[ 9*64*128];
__device__ __align__(16) __nv_bfloat16 g_B0[25*48*128];
__device__ __align__(16) __nv_bfloat16 g_B1[25*48*128];
__device__ __align__(16) __nv_bfloat16 g_Bh[25*16*128];

__device__ __forceinline__ float sigm_(float x) { return 1.f / (1.f + expf(-x)); }

__device__ __forceinline__ uint32_t smem_u32(const void* p) {
    uint32_t a;
    asm("{ .reg .u64 t; cvta.to.shared.u64 t, %1; cvt.u32.u64 %0, t; }" : "=r"(a) : "l"(p));
    return a;
}
__device__ __forceinline__ void cp16(uint32_t sdst, const void* gsrc) {
    asm volatile("cp.async.ca.shared.global [%0], [%1], 16;" :: "r"(sdst), "l"(gsrc));
}
#define CP_COMMIT() asm volatile("cp.async.commit_group;" ::: "memory")
#define CP_WAIT1()  asm volatile("cp.async.wait_group 1;" ::: "memory")
#define CP_WAIT0()  asm volatile("cp.async.wait_group 0;" ::: "memory")

#define LDSM4(r, addr)                                                          \
    asm volatile("ldmatrix.sync.aligned.m8n8.x4.shared.b16 {%0,%1,%2,%3}, [%4];"\
        : "=r"((r)[0]), "=r"((r)[1]), "=r"((r)[2]), "=r"((r)[3]) : "r"(addr))
#define LDSM2(r, addr)                                                          \
    asm volatile("ldmatrix.sync.aligned.m8n8.x2.shared.b16 {%0,%1}, [%2];"      \
        : "=r"((r)[0]), "=r"((r)[1]) : "r"(addr))
#define MMA16816(d, a, b)                                                       \
    asm volatile("mma.sync.aligned.m16n8k16.row.col.f32.bf16.bf16.f32 "         \
        "{%0,%1,%2,%3}, {%4,%5,%6,%7}, {%8,%9}, {%0,%1,%2,%3};"                 \
        : "+f"((d)[0]), "+f"((d)[1]), "+f"((d)[2]), "+f"((d)[3])                \
        : "r"((a)[0]), "r"((a)[1]), "r"((a)[2]), "r"((a)[3]),                   \
          "r"((b)[0]), "r"((b)[1]))

__device__ __forceinline__ uint32_t pk2(float a, float b) {
    __nv_bfloat162 t = __floats2bfloat162_rn(a, b);
    return *(uint32_t*)&t;
}
// split 40 fp32 -> packed 80 bf16 (hi pairs then lo pairs), 10x uint4 store
__device__ __forceinline__ void store_packed(__nv_bfloat16* dst, const float* v) {
    uint32_t w[40];
    #pragma unroll
    for (int j = 0; j < 20; ++j) {
        float a0 = v[2*j], a1 = v[2*j+1];
        float h0 = __bfloat162float(__float2bfloat16(a0));
        float h1 = __bfloat162float(__float2bfloat16(a1));
        w[j]      = pk2(h0, h1);
        w[20 + j] = pk2(a0 - h0, a1 - h1);
    }
    uint4* o = (uint4*)dst;
    #pragma unroll
    for (int i = 0; i < 10; ++i)
        o[i] = make_uint4(w[4*i], w[4*i+1], w[4*i+2], w[4*i+3]);
}

// ---------------------------------------------------------------------------
// Setup kernels
// ---------------------------------------------------------------------------
__global__ void zero_state_kernel() {
    int i = blockIdx.x * blockDim.x + threadIdx.x;
    if (i < BB*8*HW) { g_h[i] = 0.f; g_c[i] = 0.f; }
}

__global__ void prep_weights_kernel(
    const float* __restrict__ Wf, const float* __restrict__ bf,
    const float* __restrict__ Wi, const float* __restrict__ bi,
    const float* __restrict__ Wc, const float* __restrict__ bc,
    const float* __restrict__ Wq, const float* __restrict__ bq,
    const float* __restrict__ Wh, const float* __restrict__ bh,
    const float* __restrict__ W2, const float* __restrict__ b2)
{
    int i = blockIdx.x * blockDim.x + threadIdx.x;
    if (i < 56*40*9) {
        int oc = i / 360, r = i % 360;
        float v;
        if      (oc < 8 ) v = Wf[ oc     *360 + r];
        else if (oc < 16) v = Wi[(oc-8 ) *360 + r];
        else if (oc < 24) v = Wc[(oc-16) *360 + r];
        else              v = Wq[(oc-24) *360 + r];
        g_Wg[i] = v;
    }
    if (i < 56)
        g_bg[i] = (i < 8) ? bf[i] : (i < 16) ? bi[i-8] : (i < 24) ? bc[i-16] : bq[i-24];
    if (i < 11*40*25) {
        int oc = i / 1000, r = i % 1000, c = r / 25, k = r % 25, ky = k / 5, kx = k % 5;
        float v = 0.f;
        if (oc < 8) {
            if (ky >= 1 && ky <= 3 && kx >= 1 && kx <= 3)
                v = Wh[((oc*40 + c)*3 + (ky-1))*3 + (kx-1)];
        } else {
            v = W2[(((oc-8)*40 + c)*5 + ky)*5 + kx];
        }
        g_Wh2[i] = v;
    }
    if (i < 16) g_bh2[i] = (i < 8) ? bh[i] : (i < 11) ? b2[i-8] : 0.f;
}

// B images: [tap][n][128]: k<40 -> Whi[k], k 40-79 -> Whi[k-40], 80-119 -> Wlo, 120-127 -> 0
__global__ void prep_B_kernel(const float* __restrict__ W, __nv_bfloat16* __restrict__ dst,
                              int ntaps, int NPAD, int ocv)
{
    int i = blockIdx.x * blockDim.x + threadIdx.x;
    if (i >= ntaps * NPAD * 128) return;
    int k = i & 127, n = (i >> 7) % NPAD, tap = i / (128 * NPAD);
    float v = 0.f;
    if (k < 120 && n < ocv) {
        int c = k % 40;
        float w  = W[(n*40 + c)*ntaps + tap];
        float hi = __bfloat162float(__float2bfloat16(w));
        v = (k < 80) ? hi : (w - hi);
    }
    dst[i] = __float2bfloat16(v);
}

// ---------------------------------------------------------------------------
// Input transforms -> packed pixel-major bf16 hi/lo
// ---------------------------------------------------------------------------
__global__ void transform_cat_kernel(const float* __restrict__ x, int t,
                                     __nv_bfloat16* __restrict__ dst)
{
    int i = blockIdx.x * blockDim.x + threadIdx.x;
    if (i >= BB*HW) return;
    int b = i / HW, p = i - b*HW;
    float v[40];
    const float* xb = x + ((size_t)(b*DD + t)*32)*HW + p;
    #pragma unroll
    for (int c = 0; c < 32; ++c) v[c] = __ldg(&xb[(size_t)c*HW]);
    const float* hb = g_h + ((size_t)b*8)*HW + p;
    #pragma unroll
    for (int c = 0; c < 8; ++c) v[32+c] = __ldg(&hb[(size_t)c*HW]);
    store_packed(dst + (size_t)i*80, v);
}

__global__ void transform_bn_kernel(const float* __restrict__ src,
                                    const float* __restrict__ sc,
                                    const float* __restrict__ sh,
                                    __nv_bfloat16* __restrict__ dst)
{
    int i = blockIdx.x * blockDim.x + threadIdx.x;
    if (i >= BB*HW) return;
    int b = i / HW, p = i - b*HW;
    float v[40];
    const float* sb = src + ((size_t)b*40)*HW + p;
    #pragma unroll
    for (int c = 0; c < 40; ++c)
        v[c] = fmaxf(__ldg(&sb[(size_t)c*HW]) * sc[c] + sh[c], 0.f);
    store_packed(dst + (size_t)i*80, v);
}

// ---------------------------------------------------------------------------
// HMMA implicit-GEMM conv (mma.sync m16n8k16 bf16, 3-product split).
// Block: 128 pixels x NPAD oc; 8 warps as 4(M) x 2(N); warp: m32 (2 m16
// tiles) x NPAD/2 (BT n8 tiles). A smem: 128 rows x 176B (groups 0-9 =
// [hi40|lo40]); k-steps 5-7 alias the hi groups while B carries Wlo.
// B smem double-buffered [n][k] rows padded to 272B (odd 16B count ->
// conflict-free ldmatrix). Epilogue via smem D tile, 1 thread = 1 pixel.
// EPI: 0 = gate + fused LSTM (writes g_c + packed g_rt)
//      1 = planar fp32 out (po)
//      2 = head: h-state + depth output (pout, t)
// ---------------------------------------------------------------------------
template<int KD, int NPAD, int NREAL, int EPI>
__global__ __launch_bounds__(256)
void mma_conv_kernel(const __nv_bfloat16* __restrict__ inpk,
                     const __nv_bfloat16* __restrict__ Bsrc,
                     float* __restrict__ po, float* __restrict__ pout, int t)
{
    constexpr int T    = KD*KD;
    constexpr int PAD  = KD/2;
    constexpr int BT   = NPAD/16;         // n8 tiles per warp
    constexpr int SA   = 128*176;
    constexpr int BROW = 272;
    constexpr int BSZ  = NPAD*BROW;
    constexpr int DSTR = NPAD + 5;        // D-tile floats per row (odd, cf-free)

    extern __shared__ __align__(16) char smem[];
    const uint32_t sA  = smem_u32(smem);
    const uint32_t sB0 = sA + SA;

    const int tid  = threadIdx.x;
    const int lane = tid & 31;
    const int wid  = tid >> 5;
    const int wm   = wid & 3;             // 4 M-groups
    const int wn   = wid >> 2;            // 2 N-groups
    const int mbase = wm*32;
    const int nbase = wn*(NPAD/2);

    const int b    = blockIdx.x / (HW/128);
    const int pimg0= (blockIdx.x % (HW/128)) * 128;
    const size_t bpix = (size_t)b * HW;

    // A-fill assignment: thread pair per pixel
    const int fi = tid >> 1;              // pixel index in tile 0..127
    const int fh = tid & 1;               // half: 0=hi(groups0-4), 1=lo(groups5-9)
    const int fpx = (pimg0 + fi) % WW, fpy = (pimg0 + fi) / WW;

    float acc[2][BT][4];
    #pragma unroll
    for (int mt = 0; mt < 2; ++mt)
        #pragma unroll
        for (int j = 0; j < BT; ++j)
            #pragma unroll
            for (int q = 0; q < 4; ++q) acc[mt][j][q] = 0.f;

    // ---- B prefetch for tap 0 ----
    {
        const char* src = (const char*)Bsrc;
        #pragma unroll 4
        for (int idx = tid; idx < NPAD*16; idx += 256)
            cp16(sB0 + (idx >> 4)*BROW + (idx & 15)*16, src + idx*16);
        CP_COMMIT();
    }

    const int G0[8] = {0, 2, 4, 6, 8, 0, 2, 4};   // A k-group aliasing table

    for (int tap = 0; tap < T; ++tap) {
        __syncthreads();   // previous tap's fragment reads complete
        // ---- A fill (this tap) ----
        {
            int dy = tap / KD - PAD, dx = tap % KD - PAD;
            int sy = fpy + dy, sx = fpx + dx;
            uint32_t dst = sA + fi*176 + fh*80;
            if ((unsigned)sy < HH && (unsigned)sx < WW) {
                const char* src = (const char*)inpk
                    + (bpix + (size_t)(pimg0 + fi + dy*WW + dx))*160 + fh*80;
                #pragma unroll
                for (int j = 0; j < 5; ++j) cp16(dst + j*16, src + j*16);
            } else {
                #pragma unroll
                for (int j = 0; j < 5; ++j)
                    *(uint4*)(smem + (dst - sA) + j*16) = make_uint4(0,0,0,0);
            }
            CP_COMMIT();
        }
        // ---- B prefetch (next tap) ----
        if (tap + 1 < T) {
            const char* src = (const char*)Bsrc + (size_t)(tap+1)*NPAD*256;
            uint32_t dstb = sB0 + ((tap+1) & 1)*BSZ;
            #pragma unroll 4
            for (int idx = tid; idx < NPAD*16; idx += 256)
                cp16(dstb + (idx >> 4)*BROW + (idx & 15)*16, src + idx*16);
        }
        CP_COMMIT();
        CP_WAIT1();        // A(tap) + B(tap) complete; B(tap+1) in flight
        __syncthreads();

        // ---- compute 8 k-steps ----
        const uint32_t aB = sB0 + (tap & 1)*BSZ;
        const uint32_t raBase = sA + (mbase + (lane & 15))*176 + ((lane >> 4))*16;
        #pragma unroll
        for (int ks = 0; ks < 8; ++ks) {
            uint32_t a0[4], a1[4];
            uint32_t ra = raBase + G0[ks]*16;
            LDSM4(a0, ra);
            LDSM4(a1, ra + 16*176);
            uint32_t rbBase = aB + (nbase + (lane & 7))*BROW
                            + (2*ks + ((lane >> 3) & 1))*16;
            #pragma unroll
            for (int j = 0; j < BT; ++j) {
                uint32_t b2[2];
                LDSM2(b2, rbBase + j*8*BROW);
                MMA16816(acc[0][j], a0, b2);
                MMA16816(acc[1][j], a1, b2);
            }
        }
    }

    CP_WAIT0();
    __syncthreads();       // all fragment reads done before D-tile aliases smem

    // ---- write D fragments to smem D tile ----
    {
        float* sD = (float*)smem;
        int r0 = mbase + (lane >> 2);
        int c0 = nbase + 2*(lane & 3);
        #pragma unroll
        for (int mt = 0; mt < 2; ++mt) {
            #pragma unroll
            for (int j = 0; j < BT; ++j) {
                int rr = r0 + mt*16, cc = c0 + j*8;
                sD[(rr    )*DSTR + cc    ] = acc[mt][j][0];
                sD[(rr    )*DSTR + cc + 1] = acc[mt][j][1];
                sD[(rr + 8)*DSTR + cc    ] = acc[mt][j][2];
                sD[(rr + 8)*DSTR + cc + 1] = acc[mt][j][3];
            }
        }
    }
    __syncthreads();

    // ---- per-pixel epilogue (threads 0-127, thread = pixel) ----
    if (tid < 128) {
        const float* sD = (const float*)smem + tid*DSTR;
        const int pimg = pimg0 + tid;
        if (EPI == 0) {
            float v[40];
            float* C = g_c + bpix*8/HW*0 + (size_t)b*8*HW + pimg;
            #pragma unroll
            for (int c = 0; c < 8; ++c) {
                float f  = sigm_(sD[c]      + g_bg[c]);
                float ii = sigm_(sD[8 + c]  + g_bg[8 + c]);
                float gg = tanhf(sD[16 + c] + g_bg[16 + c]);
                float cs = f * C[(size_t)c*HW] + ii * gg;
                C[(size_t)c*HW] = cs;
                v[c] = cs;
            }
            #pragma unroll
            for (int j = 0; j < 32; ++j) v[8+j] = sigm_(sD[24+j] + g_bg[24+j]);
            store_packed(g_rt + (bpix + pimg)*80, v);
        } else if (EPI == 1) {
            float* O = po + (size_t)b*40*HW + pimg;
            #pragma unroll
            for (int c = 0; c < 40; ++c) O[(size_t)c*HW] = sD[c];
        } else {
            float* Hh = g_h + (size_t)b*8*HW + pimg;
            #pragma unroll
            for (int c = 0; c < 8; ++c) Hh[(size_t)c*HW] = sD[c] + g_bh2[c];
            #pragma unroll
            for (int j = 0; j < 3; ++j)
                pout[(((size_t)b*3 + j)*DD + t)*HW + pimg] = sD[8+j] + g_bh2[8+j];
        }
    }
}

// ---------------------------------------------------------------------------
// Deterministic training-mode BN stats
// ---------------------------------------------------------------------------
__global__ void bn_stats_kernel(const float* __restrict__ x,
                                const float* __restrict__ gamma,
                                const float* __restrict__ beta,
                                float* __restrict__ scale,
                                float* __restrict__ shift)
{
    const int c = blockIdx.x;
    float s = 0.f, q = 0.f;
    for (int b = 0; b < BB; ++b) {
        const float4* p = (const float4*)(x + ((size_t)b*40 + c)*HW);
        for (int i = threadIdx.x; i < HW/4; i += blockDim.x) {
            float4 v = __ldg(&p[i]);
            s += v.x + v.y + v.z + v.w;
            q += v.x*v.x + v.y*v.y + v.z*v.z + v.w*v.w;
        }
    }
    __shared__ float ss[32], sq[32];
    #pragma unroll
    for (int o = 16; o; o >>= 1) {
        s += __shfl_xor_sync(~0u, s, o);
        q += __shfl_xor_sync(~0u, q, o);
    }
    int lane = threadIdx.x & 31, w = threadIdx.x >> 5;
    if (!lane) { ss[w] = s; sq[w] = q; }
    __syncthreads();
    if (threadIdx.x < 32) {
        int nw = blockDim.x >> 5;
        s = (threadIdx.x < nw) ? ss[threadIdx.x] : 0.f;
        q = (threadIdx.x < nw) ? sq[threadIdx.x] : 0.f;
        #pragma unroll
        for (int o = 16; o; o >>= 1) {
            s += __shfl_xor_sync(~0u, s, o);
            q += __shfl_xor_sync(~0u, q, o);
        }
        if (threadIdx.x == 0) {
            const float Nn = (float)(BB*HW);
            float m  = s / Nn;
            float vv = q / Nn - m*m;
            float sc = gamma[c] * rsqrtf(vv + 1e-5f);
            scale[c] = sc;
            shift[c] = beta[c] - m*sc;
        }
    }
}

// ---------------------------------------------------------------------------
// Host driver
// ---------------------------------------------------------------------------
extern "C" void kernel_launch(void* const* d_in, const int* in_sizes, int n_in,
                              void* d_out, int out_size)
{
    const float* x1  = (const float*)d_in[0];
    const float* x2  = (const float*)d_in[1];
    const float* Wf  = (const float*)d_in[2];
    const float* bf  = (const float*)d_in[3];
    const float* Wi  = (const float*)d_in[4];
    const float* bi  = (const float*)d_in[5];
    const float* Wc  = (const float*)d_in[6];
    const float* bc  = (const float*)d_in[7];
    const float* Wq  = (const float*)d_in[8];
    const float* bq  = (const float*)d_in[9];
    const float* W0  = (const float*)d_in[10];
    const float* g0  = (const float*)d_in[11];
    const float* be0 = (const float*)d_in[12];
    const float* W1  = (const float*)d_in[13];
    const float* g1  = (const float*)d_in[14];
    const float* be1 = (const float*)d_in[15];
    const float* W2  = (const float*)d_in[16];
    const float* b2w = (const float*)d_in[17];
    const float* Wh  = (const float*)d_in[18];
    const float* bh  = (const float*)d_in[19];
    float* out = (float*)d_out;

    float *px0, *px1, *pWg, *pWh2, *psc0, *psh0, *psc1, *psh1;
    __nv_bfloat16 *pint, *prt, *px0t, *px1t, *pBg, *pB0, *pB1, *pBh;
    cudaGetSymbolAddress((void**)&px0,  g_x0);
    cudaGetSymbolAddress((void**)&px1,  g_x1);
    cudaGetSymbolAddress((void**)&pWg,  g_Wg);
    cudaGetSymbolAddress((void**)&pWh2, g_Wh2);
    cudaGetSymbolAddress((void**)&psc0, g_sc0);
    cudaGetSymbolAddress((void**)&psh0, g_sh0);
    cudaGetSymbolAddress((void**)&psc1, g_sc1);
    cudaGetSymbolAddress((void**)&psh1, g_sh1);
    cudaGetSymbolAddress((void**)&pint, g_int);
    cudaGetSymbolAddress((void**)&prt,  g_rt);
    cudaGetSymbolAddress((void**)&px0t, g_x0t);
    cudaGetSymbolAddress((void**)&px1t, g_x1t);
    cudaGetSymbolAddress((void**)&pBg,  g_Bg);
    cudaGetSymbolAddress((void**)&pB0,  g_B0);
    cudaGetSymbolAddress((void**)&pB1,  g_B1);
    cudaGetSymbolAddress((void**)&pBh,  g_Bh);

    // dynamic smem limits (idempotent; not stream ops)
    constexpr int SM_G = 128*176 + 2*64*272;   // 57344
    constexpr int SM_C = 128*176 + 2*48*272;   // 48640
    constexpr int SM_H = 128*176 + 2*16*272;   // 31232
    cudaFuncSetAttribute(mma_conv_kernel<3,64,56,0>,
                         cudaFuncAttributeMaxDynamicSharedMemorySize, SM_G);
    cudaFuncSetAttribute(mma_conv_kernel<5,48,40,1>,
                         cudaFuncAttributeMaxDynamicSharedMemorySize, SM_C);
    cudaFuncSetAttribute(mma_conv_kernel<5,16,11,2>,
                         cudaFuncAttributeMaxDynamicSharedMemorySize, SM_H);

    zero_state_kernel<<<(BB*8*HW + 255)/256, 256>>>();
    prep_weights_kernel<<<(56*40*9 + 255)/256, 256>>>(Wf, bf, Wi, bi, Wc, bc, Wq, bq,
                                                      Wh, bh, W2, b2w);
    prep_B_kernel<<<( 9*64*128 + 255)/256, 256>>>(pWg,  pBg,  9, 64, 56);
    prep_B_kernel<<<(25*48*128 + 255)/256, 256>>>(W0,   pB0, 25, 48, 40);
    prep_B_kernel<<<(25*48*128 + 255)/256, 256>>>(W1,   pB1, 25, 48, 40);
    prep_B_kernel<<<(25*16*128 + 255)/256, 256>>>(pWh2, pBh, 25, 16, 11);

    const size_t O2_OFF = (size_t)BB*3*DD*HW;
    const int NT = BB*HW/128;           // 1152 tiles
    const int NP = (BB*HW + 255)/256;   // 576 pointwise blocks

    for (int t = 0; t < DD; ++t) {
        for (int phase = 0; phase < 2; ++phase) {
            const float* xin   = phase ? x2 : x1;
            float*       obase = out + (phase ? O2_OFF : 0);

            transform_cat_kernel<<<NP, 256>>>(xin, t, pint);

            // gate conv + fused LSTM -> g_c, packed g_rt
            mma_conv_kernel<3,64,56,0><<<NT, 256, SM_G>>>(pint, pBg, nullptr, nullptr, 0);

            // conv0 -> planar x0
            mma_conv_kernel<5,48,40,1><<<NT, 256, SM_C>>>(prt, pB0, px0, nullptr, 0);
            bn_stats_kernel<<<40, 512>>>(px0, g0, be0, psc0, psh0);
            transform_bn_kernel<<<NP, 256>>>(px0, psc0, psh0, px0t);

            // conv1 -> planar x1
            mma_conv_kernel<5,48,40,1><<<NT, 256, SM_C>>>(px0t, pB1, px1, nullptr, 0);
            bn_stats_kernel<<<40, 512>>>(px1, g1, be1, psc1, psh1);
            transform_bn_kernel<<<NP, 256>>>(px1, psc1, psh1, px1t);

            // head -> h-state + depth output
            mma_conv_kernel<5,16,11,2><<<NT, 256, SM_H>>>(px1t, pBh, nullptr, obase, t);
        }
    }
}